// round 5
// baseline (speedup 1.0000x reference)
#include <cuda_runtime.h>
#include <cstdint>

typedef unsigned long long u64;
typedef unsigned int u32;

#define NP 131072
#define NC 128
#define TPB 128
#define NBLK (NP / TPB)   // 1024

// layout A (per center, 3 x float4): {cx,cy,cz,M00} {M10,M20,M01,M11} {M21,M02,M12,M22}
__device__ __align__(16) float g_paramsA[NC * 12];
// layout B (per pair of centers, 12 x float2 = 6 x float4):
// coef order: -cx,-cy,-cz,M00,M10,M20,M01,M11,M21,M02,M12,M22 ; each as (c_even, c_odd)
__device__ __align__(16) float g_paramsB[NC * 12];
__device__ float g_partial[NBLK];

// ---------------------------------------------------------------------------
// Setup (parallel over centers): identical numerics to the passing R4 kernel.
// ---------------------------------------------------------------------------
__global__ void setup_kernel(const float* __restrict__ centers,
                             const float* __restrict__ radii,
                             const float* __restrict__ rot) {
    if (threadIdx.x != 0) return;
    int c = blockIdx.x;
    float d[3];
#pragma unroll
    for (int i = 0; i < 3; i++)
        d[i] = __fdiv_rn(1.0f, __fadd_rn(fabsf(radii[c * 3 + i]), 1e-8f));

    float ax = rot[c * 3 + 0], ay = rot[c * 3 + 1], az = rot[c * 3 + 2];
    float cx = (float)cos((double)ax), sx = (float)sin((double)ax);
    float cy = (float)cos((double)ay), sy = (float)sin((double)ay);
    float cz = (float)cos((double)az), sz = (float)sin((double)az);

    float R[3][3];
    R[0][0] = __fmul_rn(cz, cy);
    R[0][1] = __fsub_rn(__fmul_rn(__fmul_rn(cz, sy), sx), __fmul_rn(sz, cx));
    R[0][2] = __fadd_rn(__fmul_rn(__fmul_rn(cz, sy), cx), __fmul_rn(sz, sx));
    R[1][0] = __fmul_rn(sz, cy);
    R[1][1] = __fadd_rn(__fmul_rn(__fmul_rn(sz, sy), sx), __fmul_rn(cz, cx));
    R[1][2] = __fsub_rn(__fmul_rn(__fmul_rn(sz, sy), cx), __fmul_rn(cz, sx));
    R[2][0] = -sy;
    R[2][1] = __fmul_rn(cy, sx);
    R[2][2] = __fmul_rn(cy, cx);

    float tmp[3][3];
#pragma unroll
    for (int a = 0; a < 3; a++)
#pragma unroll
        for (int b = 0; b < 3; b++)
            tmp[a][b] = __fmul_rn(R[a][b], d[b]);

    float M[3][3];
#pragma unroll
    for (int a = 0; a < 3; a++)
#pragma unroll
        for (int cc = 0; cc < 3; cc++)
            M[a][cc] = __fadd_rn(__fadd_rn(__fmul_rn(tmp[a][0], R[cc][0]),
                                           __fmul_rn(tmp[a][1], R[cc][1])),
                                 __fmul_rn(tmp[a][2], R[cc][2]));

    float px = centers[c * 3 + 0], py = centers[c * 3 + 1], pz = centers[c * 3 + 2];

    float* oA = g_paramsA + c * 12;
    oA[0] = px;      oA[1] = py;      oA[2] = pz;      oA[3] = M[0][0];
    oA[4] = M[1][0]; oA[5] = M[2][0]; oA[6] = M[0][1]; oA[7] = M[1][1];
    oA[8] = M[2][1]; oA[9] = M[0][2]; oA[10] = M[1][2]; oA[11] = M[2][2];

    float coef[12] = {-px, -py, -pz, M[0][0], M[1][0], M[2][0],
                      M[0][1], M[1][1], M[2][1], M[0][2], M[1][2], M[2][2]};
    float* oB = g_paramsB + (c >> 1) * 24 + (c & 1);
#pragma unroll
    for (int k = 0; k < 12; k++) oB[k * 2] = coef[k];
}

// ---------------------------------------------------------------------------
// f32x2 SIMD helpers (per-lane .rn — bit-identical to scalar ops)
// ---------------------------------------------------------------------------
__device__ __forceinline__ u64 f2add(u64 a, u64 b) {
    u64 d; asm("add.rn.f32x2 %0, %1, %2;" : "=l"(d) : "l"(a), "l"(b)); return d;
}
__device__ __forceinline__ u64 f2mul(u64 a, u64 b) {
    u64 d; asm("mul.rn.f32x2 %0, %1, %2;" : "=l"(d) : "l"(a), "l"(b)); return d;
}
__device__ __forceinline__ u64 f2fma(u64 a, u64 b, u64 c) {
    u64 d; asm("fma.rn.f32x2 %0, %1, %2, %3;" : "=l"(d) : "l"(a), "l"(b), "l"(c)); return d;
}
__device__ __forceinline__ u64 fpack(float lo, float hi) {
    u64 d; asm("mov.b64 %0, {%1, %2};" : "=l"(d) : "f"(lo), "f"(hi)); return d;
}
__device__ __forceinline__ void funpack(float& lo, float& hi, u64 v) {
    asm("mov.b64 {%0, %1}, %2;" : "=f"(lo), "=f"(hi) : "l"(v));
}

// ---------------------------------------------------------------------------
// u32 sorting network, ascending (IMNMX-only compare-exchange)
// ---------------------------------------------------------------------------
__device__ __forceinline__ void ce_asc(u32& a, u32& b) {
    u32 lo = min(a, b);
    u32 hi = max(a, b);
    a = lo; b = hi;
}

__device__ __forceinline__ void sort16_asc(u32 v[16]) {
#pragma unroll
    for (int p = 1; p < 16; p <<= 1) {
#pragma unroll
        for (int k = p; k >= 1; k >>= 1) {
#pragma unroll
            for (int j = k & (p - 1); j + k < 16; j += 2 * k) {
#pragma unroll
                for (int i = 0; i < k && (i + j + k) < 16; i++) {
                    if (((i + j) / (2 * p)) == ((i + j + k) / (2 * p))) {
                        ce_asc(v[i + j], v[i + j + k]);
                    }
                }
            }
        }
    }
}

// R asc, C asc -> R = smallest 16 of union (asc); r17 accumulates min(discarded)
__device__ __forceinline__ void merge16_asc(u32 R[16], const u32 C[16], u32& r17) {
    u32 hi[16];
#pragma unroll
    for (int i = 0; i < 16; i++) {
        u32 b = C[15 - i];
        u32 lo = min(R[i], b);
        hi[i] = max(R[i], b);
        R[i] = lo;
    }
    // min-tree over discarded
#pragma unroll
    for (int s = 8; s >= 1; s >>= 1)
#pragma unroll
        for (int i = 0; i < s; i++) hi[i] = min(hi[i], hi[i + s]);
    r17 = min(r17, hi[0]);
    // clean bitonic sequence
#pragma unroll
    for (int d = 8; d >= 1; d >>= 1) {
#pragma unroll
        for (int i = 0; i < 16; i++) {
            if ((i & d) == 0) ce_asc(R[i], R[i + d]);
        }
    }
}

__device__ __forceinline__ float ex2_fast(float x) {
    float r;
    asm("ex2.approx.f32 %0, %1;" : "=f"(r) : "f"(x));
    return r;
}

// Scalar quadratic form from layout A — bit-identical grouping to R4.
__device__ __forceinline__ float quadA(const float4* sA, int c,
                                       float x, float y, float z) {
    float4 a0 = sA[c * 3 + 0];
    float4 a1 = sA[c * 3 + 1];
    float4 a2 = sA[c * 3 + 2];
    float dx = x - a0.x, dy = y - a0.y, dz = z - a0.z;
    float t0 = fmaf(dz, a1.y, fmaf(dy, a1.x, __fmul_rn(dx, a0.w)));
    float t1 = fmaf(dz, a2.x, fmaf(dy, a1.w, __fmul_rn(dx, a1.z)));
    float t2 = fmaf(dz, a2.w, fmaf(dy, a2.z, __fmul_rn(dx, a2.y)));
    return __fadd_rn(__fadd_rn(__fmul_rn(t0, dx), __fmul_rn(t1, dy)),
                     __fmul_rn(t2, dz));
}

// ---------------------------------------------------------------------------
// Main: one thread per point.
// ---------------------------------------------------------------------------
__global__ void __launch_bounds__(TPB, 4)
main_kernel(const float* __restrict__ xyz,
            const float4* __restrict__ rgbs,
            const float* __restrict__ dists,
            float* __restrict__ out) {
    __shared__ float4 sA[NC * 3];      // 6 KB
    __shared__ float4 sB[NC * 3];      // 6 KB (pair layout: 64 pairs x 6 float4)
    __shared__ float sred[TPB];

    int tid = threadIdx.x;
#pragma unroll
    for (int i = tid; i < NC * 3; i += TPB) {
        sA[i] = reinterpret_cast<const float4*>(g_paramsA)[i];
        sB[i] = reinterpret_cast<const float4*>(g_paramsB)[i];
    }
    __syncthreads();

    int p = blockIdx.x * TPB + tid;
    float x = xyz[3 * p + 0];
    float y = xyz[3 * p + 1];
    float z = xyz[3 * p + 2];
    u64 xx2 = fpack(x, x), yy2 = fpack(y, y), zz2 = fpack(z, z);

    u32 R[16];
    u32 r17 = 0xFFFFFFFFu;
    float pen = 0.0f;
    const float CEXP = -0.72134752044448170f;  // -0.5*log2(e)
    const float K_ADD = 2.3219280948873623f;   // log2(5)

#pragma unroll 1
    for (int base = 0; base < 8; base++) {
        u32 C[16];
#pragma unroll
        for (int jp = 0; jp < 8; jp++) {
            int pair = base * 8 + jp;
            const ulonglong2* pb = reinterpret_cast<const ulonglong2*>(sB) + pair * 3;
            ulonglong2 b0 = pb[0], b1 = pb[1], b2 = pb[2];
            // b0 = {(-cx2),(-cy2)}, b1 = {(-cz2),(M00)}, then coefs per layout
            const ulonglong2* pb2 = pb;  // 6 u64s total spread over 3 ulonglong2
            u64 ncx2 = b0.x, ncy2 = b0.y, ncz2 = b1.x, m00 = b1.y;
            u64 m10 = b2.x, m20 = b2.y;
            ulonglong2 b3 = reinterpret_cast<const ulonglong2*>(sB)[pair * 3 + 0 + 0];
            (void)pb2; (void)b3;
            // remaining 6 coefs live in the NEXT 3 u64-pairs region:
            // layout B is 12 float2 per pair = 6 ulonglong2? No: 12*8B = 96B = 6 x 16B.
            const ulonglong2* pbf = reinterpret_cast<const ulonglong2*>(
                reinterpret_cast<const char*>(sB)) + pair * 6;
            ulonglong2 c0 = pbf[0], c1 = pbf[1], c2 = pbf[2],
                       c3 = pbf[3], c4 = pbf[4], c5 = pbf[5];
            ncx2 = c0.x; ncy2 = c0.y; ncz2 = c1.x; m00 = c1.y;
            m10 = c2.x;  m20 = c2.y;
            u64 m01 = c3.x, m11 = c3.y, m21 = c4.x, m02 = c4.y;
            u64 m12 = c5.x, m22 = c5.y;

            u64 dx2 = f2add(xx2, ncx2);
            u64 dy2 = f2add(yy2, ncy2);
            u64 dz2 = f2add(zz2, ncz2);
            u64 t0 = f2fma(dz2, m20, f2fma(dy2, m10, f2mul(dx2, m00)));
            u64 t1 = f2fma(dz2, m21, f2fma(dy2, m11, f2mul(dx2, m01)));
            u64 t2 = f2fma(dz2, m22, f2fma(dy2, m12, f2mul(dx2, m02)));
            u64 q2 = f2add(f2add(f2mul(t0, dx2), f2mul(t1, dy2)),
                           f2mul(t2, dz2));
            float qa, qb;
            funpack(qa, qb, q2);

            int ca = base * 16 + jp * 2;
            float ea = ex2_fast(fmaf(qa, CEXP, K_ADD));
            float eb = ex2_fast(fmaf(qb, CEXP, K_ADD));
            pen += fmaxf(ea - 0.01f, 0.0f);
            pen += fmaxf(eb - 0.01f, 0.0f);
            u32 ba = __float_as_uint(fmaxf(qa, 0.0f));
            u32 bb = __float_as_uint(fmaxf(qb, 0.0f));
            C[jp * 2 + 0] = (ba & 0xFFFFFF80u) | (u32)ca;
            C[jp * 2 + 1] = (bb & 0xFFFFFF80u) | (u32)(ca + 1);
        }
        sort16_asc(C);
        if (base == 0) {
#pragma unroll
            for (int i = 0; i < 16; i++) R[i] = C[i];
        } else {
            merge16_asc(R, C, r17);
        }
    }

    u32 cs[16];
#pragma unroll
    for (int i = 0; i < 16; i++) cs[i] = R[i] & 0x7Fu;

    // Exact fallback: truncated 16/17 boundary tie -> redo selection exactly.
    if (((R[15] ^ r17) & 0xFFFFFF80u) == 0u) {
        u64 prev = 0ull;
#pragma unroll 1
        for (int r = 0; r < 16; r++) {
            u64 best = ~0ull;
#pragma unroll 1
            for (int c = 0; c < NC; c++) {
                float q = quadA(sA, c, x, y, z);
                u32 qb = __float_as_uint(fmaxf(q, 0.0f));
                u64 k = (((u64)qb << 7) | (u32)c) + 1ull;
                if (k > prev && k < best) best = k;
            }
            prev = best;
            cs[r] = (u32)((best - 1ull) & 0x7Full);
        }
    }

    // decode: recompute exact q per selected center; w = 5*2^(qc*CEXP)
    float wv[16];
    float sumw = 0.0f;
#pragma unroll
    for (int i = 0; i < 16; i++) {
        float q = quadA(sA, (int)cs[i], x, y, z);
        float qc = fmaxf(q, 0.0f);
        float w = __fmul_rn(5.0f, ex2_fast(__fmul_rn(qc, CEXP)));
        w = (w >= 0.01f) ? w : 0.0f;
        wv[i] = w;
        sumw += w;
    }

    float inv = __fdiv_rn(1.0f, __fadd_rn(sumw, 1e-7f));
    float dp = dists[p];
    const float LOG2E = 1.4426950408889634f;

    float o0 = 0.0f, o1 = 0.0f, o2 = 0.0f, o3 = 0.0f;
#pragma unroll
    for (int i = 0; i < 16; i++) {
        if (wv[i] > 0.0f) {
            float4 g = __ldg(&rgbs[(size_t)cs[i] * NP + p]);
            float alpha = 1.0f - ex2_fast(fmaxf(g.w, 0.0f) * dp * (-LOG2E));
            float s = wv[i] * inv;
            o0 = fmaf(s, g.x, o0);
            o1 = fmaf(s, g.y, o1);
            o2 = fmaf(s, g.z, o2);
            o3 = fmaf(s, alpha, o3);
        }
    }
    reinterpret_cast<float4*>(out)[p] = make_float4(o0, o1, o2, o3);

    // deterministic block reduction of penalty
    sred[tid] = pen;
    __syncthreads();
#pragma unroll
    for (int s = TPB / 2; s > 0; s >>= 1) {
        if (tid < s) sred[tid] += sred[tid + s];
        __syncthreads();
    }
    if (tid == 0) g_partial[blockIdx.x] = sred[0];
}

// ---------------------------------------------------------------------------
// Finalize: pen = 0.001 * mean + bbox penalty; deterministic order.
// ---------------------------------------------------------------------------
__global__ void finalize_kernel(const float* __restrict__ centers,
                                float* __restrict__ out, int out_size) {
    __shared__ double sd[128];
    int t = threadIdx.x;
    double s = 0.0;
#pragma unroll
    for (int i = 0; i < NBLK / 128; i++)
        s += (double)g_partial[t * (NBLK / 128) + i];
    sd[t] = s;
    __syncthreads();
    if (t == 0) {
        double tot = 0.0;
        for (int i = 0; i < 128; i++) tot += sd[i];
        float bbox = 0.0f;
        for (int i = 0; i < NC * 3; i++) {
            float v = centers[i];
            bbox += fmaxf(v - 0.5f, 0.0f) + fmaxf(-0.5f - v, 0.0f);
        }
        float pen = (float)(0.001 * tot / (double)NP) + bbox;
        if (out_size > 4 * NP) {
            out[4 * NP] = pen;
            out[out_size - 1] = pen;
        }
    }
}

// ---------------------------------------------------------------------------
extern "C" void kernel_launch(void* const* d_in, const int* in_sizes, int n_in,
                              void* d_out, int out_size) {
    const float* xyz = nullptr;
    const float* dists = nullptr;
    const float4* rgbs = nullptr;
    const float* small3[3] = {nullptr, nullptr, nullptr};
    int nsmall = 0;
    for (int i = 0; i < n_in; i++) {
        int sz = in_sizes[i];
        if (sz == NP * 3)                xyz   = (const float*)d_in[i];
        else if (sz == NC * NP * 4)      rgbs  = (const float4*)d_in[i];
        else if (sz == NP)               dists = (const float*)d_in[i];
        else if (sz == NC * 3 && nsmall < 3) small3[nsmall++] = (const float*)d_in[i];
    }
    const float* centers = small3[0];
    const float* radii   = small3[1];
    const float* rots    = small3[2];

    setup_kernel<<<NC, 32>>>(centers, radii, rots);
    main_kernel<<<NBLK, TPB>>>(xyz, rgbs, dists, (float*)d_out);
    finalize_kernel<<<1, 128>>>(centers, (float*)d_out, out_size);
}

// round 6
// speedup vs baseline: 1.7828x; 1.7828x over previous
#include <cuda_runtime.h>
#include <cstdint>

typedef unsigned int u32;

#define NP 131072
#define NC 128
#define TPB 64
#define NBLK (NP / TPB)   // 2048
#define QPAD 132          // q row stride in floats (528B, 16B-aligned, de-conflicted)

__device__ __align__(16) float g_params[NC * 12];
__device__ float g_partial[NBLK];

// ---------------------------------------------------------------------------
// Setup: one fp64 trig per thread (latency chain 6x shorter than R4/R5).
// Numerics identical to the passing R4 kernel.
// layout A per center (3 x float4): {cx,cy,cz,M00} {M10,M20,M01,M11} {M21,M02,M12,M22}
// ---------------------------------------------------------------------------
__global__ void setup_kernel(const float* __restrict__ centers,
                             const float* __restrict__ radii,
                             const float* __restrict__ rot) {
    __shared__ float strig[NC * 6];   // per center: cos0,sin0,cos1,sin1,cos2,sin2
    int t = threadIdx.x;
    if (t < NC * 6) {
        int c = t / 6, k = t % 6, axis = k >> 1;
        double a = (double)rot[c * 3 + axis];
        strig[t] = (k & 1) ? (float)sin(a) : (float)cos(a);
    }
    __syncthreads();
    if (t >= NC) return;
    int c = t;

    float d[3];
#pragma unroll
    for (int i = 0; i < 3; i++)
        d[i] = __fdiv_rn(1.0f, __fadd_rn(fabsf(radii[c * 3 + i]), 1e-8f));

    float cx = strig[c * 6 + 0], sx = strig[c * 6 + 1];
    float cy = strig[c * 6 + 2], sy = strig[c * 6 + 3];
    float cz = strig[c * 6 + 4], sz = strig[c * 6 + 5];

    float R[3][3];
    R[0][0] = __fmul_rn(cz, cy);
    R[0][1] = __fsub_rn(__fmul_rn(__fmul_rn(cz, sy), sx), __fmul_rn(sz, cx));
    R[0][2] = __fadd_rn(__fmul_rn(__fmul_rn(cz, sy), cx), __fmul_rn(sz, sx));
    R[1][0] = __fmul_rn(sz, cy);
    R[1][1] = __fadd_rn(__fmul_rn(__fmul_rn(sz, sy), sx), __fmul_rn(cz, cx));
    R[1][2] = __fsub_rn(__fmul_rn(__fmul_rn(sz, sy), cx), __fmul_rn(cz, sx));
    R[2][0] = -sy;
    R[2][1] = __fmul_rn(cy, sx);
    R[2][2] = __fmul_rn(cy, cx);

    float tmp[3][3];
#pragma unroll
    for (int a = 0; a < 3; a++)
#pragma unroll
        for (int b = 0; b < 3; b++)
            tmp[a][b] = __fmul_rn(R[a][b], d[b]);

    float M[3][3];
#pragma unroll
    for (int a = 0; a < 3; a++)
#pragma unroll
        for (int cc = 0; cc < 3; cc++)
            M[a][cc] = __fadd_rn(__fadd_rn(__fmul_rn(tmp[a][0], R[cc][0]),
                                           __fmul_rn(tmp[a][1], R[cc][1])),
                                 __fmul_rn(tmp[a][2], R[cc][2]));

    float* oA = g_params + c * 12;
    oA[0] = centers[c * 3 + 0];
    oA[1] = centers[c * 3 + 1];
    oA[2] = centers[c * 3 + 2];
    oA[3] = M[0][0];
    oA[4]  = M[1][0]; oA[5]  = M[2][0]; oA[6]  = M[0][1]; oA[7]  = M[1][1];
    oA[8]  = M[2][1]; oA[9]  = M[0][2]; oA[10] = M[1][2]; oA[11] = M[2][2];
}

// ---------------------------------------------------------------------------
// u32 sorting network, ascending — each CE is 2x IMNMX.
// ---------------------------------------------------------------------------
__device__ __forceinline__ void ce_asc(u32& a, u32& b) {
    u32 lo = min(a, b);
    u32 hi = max(a, b);
    a = lo; b = hi;
}

__device__ __forceinline__ void sort16_asc(u32 v[16]) {
#pragma unroll
    for (int p = 1; p < 16; p <<= 1) {
#pragma unroll
        for (int k = p; k >= 1; k >>= 1) {
#pragma unroll
            for (int j = k & (p - 1); j + k < 16; j += 2 * k) {
#pragma unroll
                for (int i = 0; i < k && (i + j + k) < 16; i++) {
                    if (((i + j) / (2 * p)) == ((i + j + k) / (2 * p))) {
                        ce_asc(v[i + j], v[i + j + k]);
                    }
                }
            }
        }
    }
}

// R asc, C asc -> R = 16 smallest of union, asc.
__device__ __forceinline__ void merge16_asc(u32 R[16], const u32 C[16]) {
#pragma unroll
    for (int i = 0; i < 16; i++) R[i] = min(R[i], C[15 - i]);
#pragma unroll
    for (int d = 8; d >= 1; d >>= 1) {
#pragma unroll
        for (int i = 0; i < 16; i++) {
            if ((i & d) == 0) ce_asc(R[i], R[i + d]);
        }
    }
}

__device__ __forceinline__ float ex2_fast(float x) {
    float r;
    asm("ex2.approx.f32 %0, %1;" : "=f"(r) : "f"(x));
    return r;
}

// Quadratic form — bit-identical grouping to the passing R4 kernel.
__device__ __forceinline__ float quadA(const float4* sA, int c,
                                       float x, float y, float z) {
    float4 a0 = sA[c * 3 + 0];
    float4 a1 = sA[c * 3 + 1];
    float4 a2 = sA[c * 3 + 2];
    float dx = x - a0.x, dy = y - a0.y, dz = z - a0.z;
    float t0 = fmaf(dz, a1.y, fmaf(dy, a1.x, __fmul_rn(dx, a0.w)));
    float t1 = fmaf(dz, a2.x, fmaf(dy, a1.w, __fmul_rn(dx, a1.z)));
    float t2 = fmaf(dz, a2.w, fmaf(dy, a2.z, __fmul_rn(dx, a2.y)));
    return __fadd_rn(__fadd_rn(__fmul_rn(t0, dx), __fmul_rn(t1, dy)),
                     __fmul_rn(t2, dz));
}

// ---------------------------------------------------------------------------
// Main: one thread per point. Sort pure 32-bit q keys (exact), select by
// exact 16th-smallest with index-ascending tie-break (== lax.top_k).
// ---------------------------------------------------------------------------
__global__ void __launch_bounds__(TPB, 5)
main_kernel(const float* __restrict__ xyz,
            const float4* __restrict__ rgbs,
            const float* __restrict__ dists,
            float* __restrict__ out) {
    __shared__ float4 sA[NC * 3];                    // 6 KB
    __shared__ __align__(16) float sq[TPB * QPAD];   // 33.8 KB: per-thread q rows
    __shared__ unsigned char slist[TPB * 16];        // 1 KB: selected indices
    __shared__ float sred[TPB];

    int tid = threadIdx.x;
#pragma unroll
    for (int i = tid; i < NC * 3; i += TPB)
        sA[i] = reinterpret_cast<const float4*>(g_params)[i];
    __syncthreads();

    int p = blockIdx.x * TPB + tid;
    float x = xyz[3 * p + 0];
    float y = xyz[3 * p + 1];
    float z = xyz[3 * p + 2];

    float* qrow = sq + tid * QPAD;

    u32 R[16];
    float pen = 0.0f;
    const float CEXP = -0.72134752044448170f;  // -0.5*log2(e)
    const float K_ADD = 2.3219280948873623f;   // log2(5)

    // ---- Pass 1: q for all centers -> smem row; sort pure q keys ----
#pragma unroll 1
    for (int base = 0; base < 8; base++) {
        u32 C[16];
        float4 qbuf;
#pragma unroll
        for (int j = 0; j < 16; j++) {
            int c = base * 16 + j;
            float q = quadA(sA, c, x, y, z);
            if ((j & 3) == 0) qbuf.x = q;
            else if ((j & 3) == 1) qbuf.y = q;
            else if ((j & 3) == 2) qbuf.z = q;
            else {
                qbuf.w = q;
                *reinterpret_cast<float4*>(qrow + (c - 3)) = qbuf;
            }
            float e = ex2_fast(fmaf(q, CEXP, K_ADD));
            pen += fmaxf(e - 0.01f, 0.0f);
            C[j] = __float_as_uint(fmaxf(q, 0.0f));
        }
        sort16_asc(C);
        if (base == 0) {
#pragma unroll
            for (int i = 0; i < 16; i++) R[i] = C[i];
        } else {
            merge16_asc(R, C);
        }
    }

    u32 tq = R[15];
    int n_eq = 0;
#pragma unroll
    for (int i = 0; i < 16; i++) n_eq += (R[i] == tq) ? 1 : 0;

    // ---- Pass 2: index-order scan; select exact top-16 set ----
    unsigned char* mylist = slist + tid * 16;
    int cnt = 0, eqSeen = 0;
#pragma unroll 1
    for (int c4 = 0; c4 < NC; c4 += 4) {
        float4 qv = *reinterpret_cast<const float4*>(qrow + c4);
        float qe[4] = {qv.x, qv.y, qv.z, qv.w};
#pragma unroll
        for (int k = 0; k < 4; k++) {
            u32 qb = __float_as_uint(fmaxf(qe[k], 0.0f));
            bool eq = (qb == tq);
            bool take = (qb < tq) || (eq && (eqSeen < n_eq));
            eqSeen += eq ? 1 : 0;
            if (take) {
                mylist[cnt] = (unsigned char)(c4 + k);
                cnt++;
            }
        }
    }

    // ---- Gather: 16 selected; weights decoded from the same stored q ----
    float dp = dists[p];
    const float LOG2E = 1.4426950408889634f;
    float sumw = 0.0f;
    float o0 = 0.0f, o1 = 0.0f, o2 = 0.0f, o3 = 0.0f;
#pragma unroll
    for (int i = 0; i < 16; i++) {
        int c = (int)mylist[i];
        float q = qrow[c];
        float qc = fmaxf(q, 0.0f);
        float w = __fmul_rn(5.0f, ex2_fast(__fmul_rn(qc, CEXP)));
        w = (w >= 0.01f) ? w : 0.0f;
        sumw += w;
        if (w > 0.0f) {
            float4 g = __ldg(&rgbs[(size_t)c * NP + p]);
            float alpha = 1.0f - ex2_fast(fmaxf(g.w, 0.0f) * dp * (-LOG2E));
            o0 = fmaf(w, g.x, o0);
            o1 = fmaf(w, g.y, o1);
            o2 = fmaf(w, g.z, o2);
            o3 = fmaf(w, alpha, o3);
        }
    }
    float inv = __fdiv_rn(1.0f, __fadd_rn(sumw, 1e-7f));
    reinterpret_cast<float4*>(out)[p] =
        make_float4(o0 * inv, o1 * inv, o2 * inv, o3 * inv);

    // deterministic block reduction of penalty
    sred[tid] = pen;
    __syncthreads();
#pragma unroll
    for (int s = TPB / 2; s > 0; s >>= 1) {
        if (tid < s) sred[tid] += sred[tid + s];
        __syncthreads();
    }
    if (tid == 0) g_partial[blockIdx.x] = sred[0];
}

// ---------------------------------------------------------------------------
// Finalize: pen = 0.001 * mean + bbox penalty; deterministic order.
// ---------------------------------------------------------------------------
__global__ void finalize_kernel(const float* __restrict__ centers,
                                float* __restrict__ out, int out_size) {
    __shared__ double sd[128];
    int t = threadIdx.x;
    double s = 0.0;
#pragma unroll
    for (int i = 0; i < NBLK / 128; i++)
        s += (double)g_partial[t * (NBLK / 128) + i];
    sd[t] = s;
    __syncthreads();
    if (t == 0) {
        double tot = 0.0;
        for (int i = 0; i < 128; i++) tot += sd[i];
        float bbox = 0.0f;
        for (int i = 0; i < NC * 3; i++) {
            float v = centers[i];
            bbox += fmaxf(v - 0.5f, 0.0f) + fmaxf(-0.5f - v, 0.0f);
        }
        float pen = (float)(0.001 * tot / (double)NP) + bbox;
        if (out_size > 4 * NP) {
            out[4 * NP] = pen;
            out[out_size - 1] = pen;
        }
    }
}

// ---------------------------------------------------------------------------
extern "C" void kernel_launch(void* const* d_in, const int* in_sizes, int n_in,
                              void* d_out, int out_size) {
    const float* xyz = nullptr;
    const float* dists = nullptr;
    const float4* rgbs = nullptr;
    const float* small3[3] = {nullptr, nullptr, nullptr};
    int nsmall = 0;
    for (int i = 0; i < n_in; i++) {
        int sz = in_sizes[i];
        if (sz == NP * 3)                xyz   = (const float*)d_in[i];
        else if (sz == NC * NP * 4)      rgbs  = (const float4*)d_in[i];
        else if (sz == NP)               dists = (const float*)d_in[i];
        else if (sz == NC * 3 && nsmall < 3) small3[nsmall++] = (const float*)d_in[i];
    }
    const float* centers = small3[0];
    const float* radii   = small3[1];
    const float* rots    = small3[2];

    setup_kernel<<<1, NC * 6>>>(centers, radii, rots);
    main_kernel<<<NBLK, TPB>>>(xyz, rgbs, dists, (float*)d_out);
    finalize_kernel<<<1, 128>>>(centers, (float*)d_out, out_size);
}

// round 7
// speedup vs baseline: 2.0564x; 1.1535x over previous
#include <cuda_runtime.h>
#include <cstdint>

typedef unsigned int u32;

#define NP 131072
#define NC 128
#define TPB 128
#define NBLK (NP / TPB)   // 1024

__device__ __align__(16) float g_params[NC * 12];
__device__ float g_partial[NBLK];
__device__ u32 g_done = 0;   // self-resetting via atomicInc wrap

// ---------------------------------------------------------------------------
// Setup: 128 blocks (1 per center); 6 threads do the 6 fp64 trig calls in
// parallel (chain 6x shorter than R6). Numerics identical to passing R4/R6.
// layout per center (3 x float4): {cx,cy,cz,M00} {M10,M20,M01,M11} {M21,M02,M12,M22}
// ---------------------------------------------------------------------------
__global__ void setup_kernel(const float* __restrict__ centers,
                             const float* __restrict__ radii,
                             const float* __restrict__ rot) {
    __shared__ float strig[6];
    int t = threadIdx.x;
    int c = blockIdx.x;
    if (t < 6) {
        int axis = t >> 1;
        double a = (double)rot[c * 3 + axis];
        strig[t] = (t & 1) ? (float)sin(a) : (float)cos(a);
    }
    __syncthreads();
    if (t != 0) return;

    float d[3];
#pragma unroll
    for (int i = 0; i < 3; i++)
        d[i] = __fdiv_rn(1.0f, __fadd_rn(fabsf(radii[c * 3 + i]), 1e-8f));

    float cx = strig[0], sx = strig[1];
    float cy = strig[2], sy = strig[3];
    float cz = strig[4], sz = strig[5];

    float R[3][3];
    R[0][0] = __fmul_rn(cz, cy);
    R[0][1] = __fsub_rn(__fmul_rn(__fmul_rn(cz, sy), sx), __fmul_rn(sz, cx));
    R[0][2] = __fadd_rn(__fmul_rn(__fmul_rn(cz, sy), cx), __fmul_rn(sz, sx));
    R[1][0] = __fmul_rn(sz, cy);
    R[1][1] = __fadd_rn(__fmul_rn(__fmul_rn(sz, sy), sx), __fmul_rn(cz, cx));
    R[1][2] = __fsub_rn(__fmul_rn(__fmul_rn(sz, sy), cx), __fmul_rn(cz, sx));
    R[2][0] = -sy;
    R[2][1] = __fmul_rn(cy, sx);
    R[2][2] = __fmul_rn(cy, cx);

    float tmp[3][3];
#pragma unroll
    for (int a = 0; a < 3; a++)
#pragma unroll
        for (int b = 0; b < 3; b++)
            tmp[a][b] = __fmul_rn(R[a][b], d[b]);

    float M[3][3];
#pragma unroll
    for (int a = 0; a < 3; a++)
#pragma unroll
        for (int cc = 0; cc < 3; cc++)
            M[a][cc] = __fadd_rn(__fadd_rn(__fmul_rn(tmp[a][0], R[cc][0]),
                                           __fmul_rn(tmp[a][1], R[cc][1])),
                                 __fmul_rn(tmp[a][2], R[cc][2]));

    float* oA = g_params + c * 12;
    oA[0] = centers[c * 3 + 0];
    oA[1] = centers[c * 3 + 1];
    oA[2] = centers[c * 3 + 2];
    oA[3]  = M[0][0];
    oA[4]  = M[1][0]; oA[5]  = M[2][0]; oA[6]  = M[0][1]; oA[7]  = M[1][1];
    oA[8]  = M[2][1]; oA[9]  = M[0][2]; oA[10] = M[1][2]; oA[11] = M[2][2];
}

// ---------------------------------------------------------------------------
// u32 sorting network, ascending — each CE is 2x IMNMX.
// ---------------------------------------------------------------------------
__device__ __forceinline__ void ce_asc(u32& a, u32& b) {
    u32 lo = min(a, b);
    u32 hi = max(a, b);
    a = lo; b = hi;
}

__device__ __forceinline__ void sort16_asc(u32 v[16]) {
#pragma unroll
    for (int p = 1; p < 16; p <<= 1) {
#pragma unroll
        for (int k = p; k >= 1; k >>= 1) {
#pragma unroll
            for (int j = k & (p - 1); j + k < 16; j += 2 * k) {
#pragma unroll
                for (int i = 0; i < k && (i + j + k) < 16; i++) {
                    if (((i + j) / (2 * p)) == ((i + j + k) / (2 * p))) {
                        ce_asc(v[i + j], v[i + j + k]);
                    }
                }
            }
        }
    }
}

// R asc, C asc -> R = 16 smallest of union, asc.
__device__ __forceinline__ void merge16_asc(u32 R[16], const u32 C[16]) {
#pragma unroll
    for (int i = 0; i < 16; i++) R[i] = min(R[i], C[15 - i]);
#pragma unroll
    for (int d = 8; d >= 1; d >>= 1) {
#pragma unroll
        for (int i = 0; i < 16; i++) {
            if ((i & d) == 0) ce_asc(R[i], R[i + d]);
        }
    }
}

__device__ __forceinline__ float ex2_fast(float x) {
    float r;
    asm("ex2.approx.f32 %0, %1;" : "=f"(r) : "f"(x));
    return r;
}

// Quadratic form — bit-identical grouping to the passing R4/R6 kernels.
__device__ __forceinline__ float quadA(const float4* sA, int c,
                                       float x, float y, float z) {
    float4 a0 = sA[c * 3 + 0];
    float4 a1 = sA[c * 3 + 1];
    float4 a2 = sA[c * 3 + 2];
    float dx = x - a0.x, dy = y - a0.y, dz = z - a0.z;
    float t0 = fmaf(dz, a1.y, fmaf(dy, a1.x, __fmul_rn(dx, a0.w)));
    float t1 = fmaf(dz, a2.x, fmaf(dy, a1.w, __fmul_rn(dx, a1.z)));
    float t2 = fmaf(dz, a2.w, fmaf(dy, a2.z, __fmul_rn(dx, a2.y)));
    return __fadd_rn(__fadd_rn(__fmul_rn(t0, dx), __fmul_rn(t1, dy)),
                     __fmul_rn(t2, dz));
}

// ---------------------------------------------------------------------------
// Main: one thread per point; no q spill buffer (recompute in pass2/gather)
// -> ~9KB smem -> 20 warps/SM. Integrated last-block finalize.
// ---------------------------------------------------------------------------
__global__ void __launch_bounds__(TPB, 5)
main_kernel(const float* __restrict__ xyz,
            const float4* __restrict__ rgbs,
            const float* __restrict__ dists,
            const float* __restrict__ centers,
            float* __restrict__ out, int out_size) {
    __shared__ float4 sA[NC * 3];               // 6 KB
    __shared__ unsigned char slist[TPB * 16];   // 2 KB
    __shared__ float sred[TPB];
    __shared__ bool sLast;

    int tid = threadIdx.x;
#pragma unroll
    for (int i = tid; i < NC * 3; i += TPB)
        sA[i] = reinterpret_cast<const float4*>(g_params)[i];
    __syncthreads();

    int p = blockIdx.x * TPB + tid;
    float x = xyz[3 * p + 0];
    float y = xyz[3 * p + 1];
    float z = xyz[3 * p + 2];

    u32 R[16];
    float pen = 0.0f;
    const float CEXP = -0.72134752044448170f;  // -0.5*log2(e)
    const float K_ADD = 2.3219280948873623f;   // log2(5)

    // ---- Pass 1: q for all centers; sort pure q bit-keys (exact) ----
#pragma unroll 1
    for (int base = 0; base < 8; base++) {
        u32 C[16];
#pragma unroll
        for (int j = 0; j < 16; j++) {
            int c = base * 16 + j;
            float q = quadA(sA, c, x, y, z);
            float e = ex2_fast(fmaf(q, CEXP, K_ADD));
            pen += fmaxf(e - 0.01f, 0.0f);
            C[j] = __float_as_uint(fmaxf(q, 0.0f));
        }
        sort16_asc(C);
        if (base == 0) {
#pragma unroll
            for (int i = 0; i < 16; i++) R[i] = C[i];
        } else {
            merge16_asc(R, C);
        }
    }

    u32 tq = R[15];
    int n_eq = 0;
#pragma unroll
    for (int i = 0; i < 16; i++) n_eq += (R[i] == tq) ? 1 : 0;

    // ---- Pass 2: index-order rescan (recompute q, bit-identical);
    //      exact top-16 set with index-ascending tie-break (== lax.top_k) ----
    unsigned char* mylist = slist + tid * 16;
    int cnt = 0, eqSeen = 0;
#pragma unroll 1
    for (int c = 0; c < NC; c++) {
        float q = quadA(sA, c, x, y, z);
        u32 qb = __float_as_uint(fmaxf(q, 0.0f));
        bool eq = (qb == tq);
        bool take = (qb < tq) || (eq && (eqSeen < n_eq));
        eqSeen += eq ? 1 : 0;
        if (take) {
            mylist[cnt] = (unsigned char)c;
            cnt++;
        }
    }

    // ---- Gather: 16 selected; weight decoded from recomputed q ----
    float dp = dists[p];
    const float LOG2E = 1.4426950408889634f;
    float sumw = 0.0f;
    float o0 = 0.0f, o1 = 0.0f, o2 = 0.0f, o3 = 0.0f;
#pragma unroll
    for (int i = 0; i < 16; i++) {
        int c = (int)mylist[i];
        float q = quadA(sA, c, x, y, z);
        float qc = fmaxf(q, 0.0f);
        float w = __fmul_rn(5.0f, ex2_fast(__fmul_rn(qc, CEXP)));
        w = (w >= 0.01f) ? w : 0.0f;
        sumw += w;
        if (w > 0.0f) {
            float4 g = __ldg(&rgbs[(size_t)c * NP + p]);
            float alpha = 1.0f - ex2_fast(fmaxf(g.w, 0.0f) * dp * (-LOG2E));
            o0 = fmaf(w, g.x, o0);
            o1 = fmaf(w, g.y, o1);
            o2 = fmaf(w, g.z, o2);
            o3 = fmaf(w, alpha, o3);
        }
    }
    float inv = __fdiv_rn(1.0f, __fadd_rn(sumw, 1e-7f));
    reinterpret_cast<float4*>(out)[p] =
        make_float4(o0 * inv, o1 * inv, o2 * inv, o3 * inv);

    // ---- deterministic block reduction of penalty ----
    sred[tid] = pen;
    __syncthreads();
#pragma unroll
    for (int s = TPB / 2; s > 0; s >>= 1) {
        if (tid < s) sred[tid] += sred[tid + s];
        __syncthreads();
    }
    if (tid == 0) {
        g_partial[blockIdx.x] = sred[0];
        __threadfence();
        u32 old = atomicInc(&g_done, NBLK - 1);  // wraps to 0: self-resetting
        sLast = (old == NBLK - 1);
    }
    __syncthreads();

    // ---- Last block: finalize pen (deterministic fixed-order sum) ----
    if (sLast) {
        __shared__ double sd[TPB];
        double s = 0.0;
#pragma unroll
        for (int i = 0; i < NBLK / TPB; i++)
            s += (double)g_partial[tid * (NBLK / TPB) + i];
        sd[tid] = s;
        __syncthreads();
        if (tid == 0) {
            double tot = 0.0;
            for (int i = 0; i < TPB; i++) tot += sd[i];
            float bbox = 0.0f;
            for (int i = 0; i < NC * 3; i++) {
                float v = centers[i];
                bbox += fmaxf(v - 0.5f, 0.0f) + fmaxf(-0.5f - v, 0.0f);
            }
            float pv = (float)(0.001 * tot / (double)NP) + bbox;
            if (out_size > 4 * NP) {
                out[4 * NP] = pv;
                out[out_size - 1] = pv;
            }
        }
    }
}

// ---------------------------------------------------------------------------
extern "C" void kernel_launch(void* const* d_in, const int* in_sizes, int n_in,
                              void* d_out, int out_size) {
    const float* xyz = nullptr;
    const float* dists = nullptr;
    const float4* rgbs = nullptr;
    const float* small3[3] = {nullptr, nullptr, nullptr};
    int nsmall = 0;
    for (int i = 0; i < n_in; i++) {
        int sz = in_sizes[i];
        if (sz == NP * 3)                xyz   = (const float*)d_in[i];
        else if (sz == NC * NP * 4)      rgbs  = (const float4*)d_in[i];
        else if (sz == NP)               dists = (const float*)d_in[i];
        else if (sz == NC * 3 && nsmall < 3) small3[nsmall++] = (const float*)d_in[i];
    }
    const float* centers = small3[0];
    const float* radii   = small3[1];
    const float* rots    = small3[2];

    setup_kernel<<<NC, 8>>>(centers, radii, rots);
    main_kernel<<<NBLK, TPB>>>(xyz, rgbs, dists, centers, (float*)d_out, out_size);
}